// round 9
// baseline (speedup 1.0000x reference)
#include <cuda_runtime.h>
#include <cuda_bf16.h>
#include <math.h>
#include <stdint.h>

#define SL 1024
#define HD 64
#define NBH 32
#define NS 4
#define LMAXC 2048
#define PLANE (NBH * SL * HD)

// Scratch (static device globals: allocation-free)
__device__ __nv_bfloat16 g_Mb[(size_t)NBH * SL * SL];    // |C|/8, bf16, 64MB
__device__ float g_a[NS * SL];                           // scale magnitude tables
__device__ float g_Zp[(size_t)NBH * 16 * 2 * NS * SL];   // Z partials (deterministic)
__device__ float g_sc[SL];                               // expert sum-cos per l
__device__ float g_ss[SL];                               // expert sum-sin per l

// ---------------------------------------------------------------------------
// mma.sync wrappers (sm_80+ baseline features, compile at plain sm_103)
// ---------------------------------------------------------------------------
__device__ __forceinline__ void mma1688(float* d, const uint32_t* a, const uint32_t* b) {
    asm volatile(
        "mma.sync.aligned.m16n8k8.row.col.f32.tf32.tf32.f32 "
        "{%0,%1,%2,%3}, {%4,%5,%6,%7}, {%8,%9}, {%0,%1,%2,%3};\n"
        : "+f"(d[0]), "+f"(d[1]), "+f"(d[2]), "+f"(d[3])
        : "r"(a[0]), "r"(a[1]), "r"(a[2]), "r"(a[3]), "r"(b[0]), "r"(b[1]));
}
__device__ __forceinline__ void mma16816bf(float* d, const uint32_t* a, const uint32_t* b) {
    asm volatile(
        "mma.sync.aligned.m16n8k16.row.col.f32.bf16.bf16.f32 "
        "{%0,%1,%2,%3}, {%4,%5,%6,%7}, {%8,%9}, {%0,%1,%2,%3};\n"
        : "+f"(d[0]), "+f"(d[1]), "+f"(d[2]), "+f"(d[3])
        : "r"(a[0]), "r"(a[1]), "r"(a[2]), "r"(a[3]), "r"(b[0]), "r"(b[1]));
}
__device__ __forceinline__ uint32_t f2tf32(float x) {
    uint32_t r;
    asm("cvt.rna.tf32.f32 %0, %1;" : "=r"(r) : "f"(x));
    return r;
}
__device__ __forceinline__ uint32_t pack_bf2(float a, float b) {
    __nv_bfloat162 t = __floats2bfloat162_rn(a, b);
    return *(uint32_t*)&t;
}

// 1/sqrt Newton (FMA pipe, no MUFU): rel err ~1.7e-3 — below bf16 storage error.
__device__ __forceinline__ float rsqrt1(float x) {
    float r = __int_as_float(0x5f3759df - (__float_as_int(x) >> 1));
    return r * fmaf(-0.5f * x * r, r, 1.5f);
}

// ===========================================================================
// Kernel A: a_s[l] tables + expert sums. 5 blocks: 0-3 = scales, 4 = expert.
// ===========================================================================
__device__ __forceinline__ float pmag2f(float t) {
    return 3.f + 2.f * __cosf(t) + 2.f * __cosf(0.5f * t) + 2.f * __cosf(1.5f * t);
}

__global__ __launch_bounds__(1024) void k_tables() {
    __shared__ float red[1024];
    int l = threadIdx.x;
    int b = blockIdx.x;
    if (b < 4) {
        const float freqs[NS] = {1.f, 0.5f, 0.25f, 0.1f};
        float step = 6.283185307179586f * freqs[b] / (float)(LMAXC - 1);
        float p0 = pmag2f((float)l * step);
        float p1 = pmag2f((float)(l + 1024) * step);
        red[l] = p0 + p1;
        __syncthreads();
        for (int o = 512; o > 0; o >>= 1) {
            if (l < o) red[l] += red[l + o];
            __syncthreads();
        }
        g_a[b * SL + l] = sqrtf(fmaxf(p0, 0.f)) * rsqrtf(red[0]);
    } else {
        float t = (float)l * (6.283185307179586f / (float)(LMAXC - 1));
        float sc = 0.f, ss = 0.f;
        #pragma unroll
        for (int i = 0; i < 8; i++) {
            float fb = 0.1f * (float)i;
            float s0, c0, s1, c1, s2, c2;
            __sincosf((0.3f + fb) * t, &s0, &c0);
            __sincosf((0.2f + fb) * t, &s1, &c1);
            __sincosf((0.1f + fb) * t, &s2, &c2);
            sc += c0 + c1 + c2;
            ss += s0 + s1 + s2;
        }
        g_sc[l] = sc;
        g_ss[l] = ss;
    }
}

// ===========================================================================
// Kernel B: complex scores via bf16 mma.sync m16n8k16. CTA = 128 l x 64 m.
// Warps 4(row)x2(col), each 32x32. Epilogue: M=|c|/8 -> bf16 g_Mb, plus
// separable deg-2 softmax-Z partials (exp(x)=1+x+x^2/2, x<=0.013).
// ===========================================================================
#define SC_SMEM_U32 14848

__global__ __launch_bounds__(256) void k_scores(const float* __restrict__ Qr,
                                                const float* __restrict__ Qi,
                                                const float* __restrict__ Kr,
                                                const float* __restrict__ Ki) {
    extern __shared__ uint32_t su[];
    uint32_t* sQr = su;
    uint32_t* sQi = su + 4608;
    uint32_t* sKr = su + 9216;
    uint32_t* sKi = su + 11520;
    float* sal = (float*)(su + 13824);
    float* sam = (float*)(su + 14336);
    float* sam2 = (float*)(su + 14592);

    int tid = threadIdx.x, wid = tid >> 5, lane = tid & 31;
    int g = lane >> 2, t = lane & 3;
    int mt = blockIdx.x, bh = blockIdx.z;
    int l0 = blockIdx.y * 128, m0 = mt * 64;
    int wr = wid & 3, wc = wid >> 2;

    // Stage Q (128x64) and K (64x64) as bf16 pairs, stride 36 u32 (32+4 pad)
    for (int e = tid; e < 2048; e += 256) {
        int row = e >> 4, c = e & 15;
        float4 v = *(const float4*)&Qr[((size_t)bh * SL + l0 + row) * HD + c * 4];
        uint2 w = make_uint2(pack_bf2(v.x, v.y), pack_bf2(v.z, v.w));
        *(uint2*)&sQr[row * 36 + c * 2] = w;
        v = *(const float4*)&Qi[((size_t)bh * SL + l0 + row) * HD + c * 4];
        w = make_uint2(pack_bf2(v.x, v.y), pack_bf2(v.z, v.w));
        *(uint2*)&sQi[row * 36 + c * 2] = w;
    }
    for (int e = tid; e < 1024; e += 256) {
        int row = e >> 4, c = e & 15;
        float4 v = *(const float4*)&Kr[((size_t)bh * SL + m0 + row) * HD + c * 4];
        uint2 w = make_uint2(pack_bf2(v.x, v.y), pack_bf2(v.z, v.w));
        *(uint2*)&sKr[row * 36 + c * 2] = w;
        v = *(const float4*)&Ki[((size_t)bh * SL + m0 + row) * HD + c * 4];
        w = make_uint2(pack_bf2(v.x, v.y), pack_bf2(v.z, v.w));
        *(uint2*)&sKi[row * 36 + c * 2] = w;
    }
    for (int e = tid; e < 512; e += 256)
        sal[e] = g_a[(e >> 7) * SL + l0 + (e & 127)];
    if (tid < 256) {
        float v = g_a[(tid >> 6) * SL + m0 + (tid & 63)];
        sam[tid] = v;
        sam2[tid] = v * v;
    }
    __syncthreads();

    float cr[2][4][4] = {}, ci[2][4][4] = {};
    #pragma unroll
    for (int kc = 0; kc < 4; kc++) {
        int kb = kc * 8;   // pair units (16 k per chunk)
        uint32_t aR[2][4], aI[2][4], aIn[2][4];
        #pragma unroll
        for (int mi = 0; mi < 2; mi++) {
            int rb = (wr * 32 + mi * 16 + g) * 36 + kb + t;
            aR[mi][0] = sQr[rb];
            aR[mi][1] = sQr[rb + 8 * 36];
            aR[mi][2] = sQr[rb + 4];
            aR[mi][3] = sQr[rb + 8 * 36 + 4];
            aI[mi][0] = sQi[rb];
            aI[mi][1] = sQi[rb + 8 * 36];
            aI[mi][2] = sQi[rb + 4];
            aI[mi][3] = sQi[rb + 8 * 36 + 4];
            #pragma unroll
            for (int q = 0; q < 4; q++) aIn[mi][q] = aI[mi][q] ^ 0x80008000u;
        }
        #pragma unroll
        for (int ni = 0; ni < 4; ni++) {
            int nb = (wc * 32 + ni * 8 + g) * 36 + kb + t;
            uint32_t bR[2] = {sKr[nb], sKr[nb + 4]};
            uint32_t bI[2] = {sKi[nb], sKi[nb + 4]};
            #pragma unroll
            for (int mi = 0; mi < 2; mi++) {
                mma16816bf(cr[mi][ni], aR[mi], bR);
                mma16816bf(cr[mi][ni], aIn[mi], bI);
                mma16816bf(ci[mi][ni], aR[mi], bI);
                mma16816bf(ci[mi][ni], aI[mi], bR);
            }
        }
    }

    // Epilogue: M -> bf16 g_Mb + separable deg-2 Z partials
    float S1[4][4] = {}, S2[4][4] = {};   // [ridx][s]
    size_t mrow0 = ((size_t)bh * SL + l0) * SL + m0 + wc * 32;
    #pragma unroll
    for (int ni = 0; ni < 4; ni++) {
        int c0 = ni * 8 + 2 * t;          // col within warp's 32
        float a0[4], a1[4], b0[4], b1[4];
        #pragma unroll
        for (int s = 0; s < 4; s++) {
            a0[s] = sam[s * 64 + wc * 32 + c0];
            a1[s] = sam[s * 64 + wc * 32 + c0 + 1];
            b0[s] = sam2[s * 64 + wc * 32 + c0];
            b1[s] = sam2[s * 64 + wc * 32 + c0 + 1];
        }
        #pragma unroll
        for (int mi = 0; mi < 2; mi++) {
            #pragma unroll
            for (int h = 0; h < 2; h++) {
                int ridx = mi * 2 + h;
                int row = wr * 32 + mi * 16 + g + h * 8;
                float x0 = cr[mi][ni][h * 2], y0 = ci[mi][ni][h * 2];
                float x1 = cr[mi][ni][h * 2 + 1], y1 = ci[mi][ni][h * 2 + 1];
                float h20 = fmaxf(fmaf(x0, x0, y0 * y0), 1e-30f);
                float h21 = fmaxf(fmaf(x1, x1, y1 * y1), 1e-30f);
                float Mv0 = h20 * rsqrt1(h20) * 0.125f;
                float Mv1 = h21 * rsqrt1(h21) * 0.125f;
                float M20 = h20 * 0.015625f;      // Mv^2
                float M21 = h21 * 0.015625f;
                *(__nv_bfloat162*)&g_Mb[mrow0 + (size_t)row * SL + c0] =
                    __floats2bfloat162_rn(Mv0, Mv1);
                #pragma unroll
                for (int s = 0; s < 4; s++) {
                    S1[ridx][s] = fmaf(a0[s], Mv0, fmaf(a1[s], Mv1, S1[ridx][s]));
                    S2[ridx][s] = fmaf(b0[s], M20, fmaf(b1[s], M21, S2[ridx][s]));
                }
            }
        }
    }
    #pragma unroll
    for (int ridx = 0; ridx < 4; ridx++)
        #pragma unroll
        for (int s = 0; s < 4; s++) {
            S1[ridx][s] += __shfl_xor_sync(0xffffffffu, S1[ridx][s], 1);
            S1[ridx][s] += __shfl_xor_sync(0xffffffffu, S1[ridx][s], 2);
            S2[ridx][s] += __shfl_xor_sync(0xffffffffu, S2[ridx][s], 1);
            S2[ridx][s] += __shfl_xor_sync(0xffffffffu, S2[ridx][s], 2);
        }
    if (t == 0) {
        #pragma unroll
        for (int ridx = 0; ridx < 4; ridx++) {
            int row = wr * 32 + (ridx >> 1) * 16 + g + (ridx & 1) * 8;
            #pragma unroll
            for (int s = 0; s < 4; s++) {
                float cl = sal[s * 128 + row];
                float z = fmaf(cl, S1[ridx][s], 32.f);
                z = fmaf(0.5f * cl * cl, S2[ridx][s], z);
                g_Zp[((((size_t)bh * 16 + mt) * 2 + wc) * 4 + s) * SL + l0 + row] = z;
            }
        }
    }
}

// ===========================================================================
// Kernel C: O = W @ [Vr|Vi] via tf32 mma.sync; V used in natural [m][d]
// layout as B-operand (conflict-free staging + frag loads); W generated on
// the fly (separable deg-2); SMEM epilogue pairs Or/Oi for expert multiply.
// CTA = 64 l x 128 n; warps 2(l)x4(n); 16 key-slabs of 64.
// ===========================================================================
#define AV_SMEM_FLOATS 22080

__global__ __launch_bounds__(256) void k_av(const float* __restrict__ Vr,
                                            const float* __restrict__ Vi,
                                            float* __restrict__ out) {
    extern __shared__ float sm[];
    float* sW = sm;
    float* sV = sm + 4352;
    float* samF = sm + 13056;
    float* sam2F = sm + 17152;
    float* T0 = sm + 21248;
    float* R1 = sm + 21312;
    float* R2 = sm + 21568;
    float* scp = sm + 21824;
    float* ssp = sm + 21888;
    float* sscl = sm + 21952;
    float* sssl = sm + 22016;

    int tid = threadIdx.x, wid = tid >> 5, lane = tid & 31;
    int g = lane >> 2, t = lane & 3;
    int bh = blockIdx.y, l0 = blockIdx.x * 64;
    int wr = wid & 1, wc = wid >> 1;
    const float KC = 0.00225527461f;   // 0.5 / sqrt(2048 * 24)

    for (int e = tid; e < 4096; e += 256) {
        float v = g_a[(e >> 10) * SL + (e & 1023)];
        samF[e] = v;
        sam2F[e] = v * v;
    }
    {   // per-(s,row) Z reduction, parallel over 256 threads
        int s = tid >> 6, r = tid & 63, l = l0 + r;
        float zt = 0.f;
        #pragma unroll 8
        for (int p = 0; p < 32; p++)
            zt += g_Zp[(((size_t)bh * 32 + p) * 4 + s) * SL + l];
        float riz = 1.0f / zt;
        float cl = g_a[s * SL + l];
        sW[s * 64 + r] = riz;                       // temp for T0 reduce
        R1[s * 64 + r] = riz * cl;
        R2[s * 64 + r] = 0.5f * riz * cl * cl;
    }
    if (tid < 64) {
        int r = tid, l = l0 + r;
        float sp, cp;
        __sincosf(0.09817477042f * (float)r, &sp, &cp);   // 2*pi/64 * d
        scp[r] = cp;
        ssp[r] = sp;
        sscl[r] = g_sc[l] * KC;
        sssl[r] = g_ss[l] * KC;
    }
    __syncthreads();
    if (tid < 64)
        T0[tid] = sW[tid] + sW[64 + tid] + sW[128 + tid] + sW[192 + tid];

    float acc[2][4][4] = {};
    const __nv_bfloat16* Mrow = g_Mb + ((size_t)bh * SL + l0) * SL;
    const float* vr = Vr + (size_t)bh * SL * HD;
    const float* vi = Vi + (size_t)bh * SL * HD;
    int j = tid & 63, rbase = tid >> 6;

    for (int it = 0; it < 16; it++) {
        int m0 = it * 64;
        __syncthreads();   // protect prev-iter sW/sV reads (and T0 init)
        // W tile 64l x 64m: w = T0[r] + M*A + M^2*B
        float amv[4], am2v[4];
        #pragma unroll
        for (int s = 0; s < 4; s++) {
            amv[s] = samF[s * 1024 + m0 + j];
            am2v[s] = sam2F[s * 1024 + m0 + j];
        }
        #pragma unroll
        for (int i = 0; i < 16; i++) {
            int r = rbase + i * 4;   // warp-uniform row
            float Mv = __bfloat162float(Mrow[(size_t)r * SL + m0 + j]);
            float A = 0.f, B = 0.f;
            #pragma unroll
            for (int s = 0; s < 4; s++) {
                A = fmaf(R1[s * 64 + r], amv[s], A);
                B = fmaf(R2[s * 64 + r], am2v[s], B);
            }
            float w = fmaf(Mv, A, T0[r]);
            w = fmaf(Mv * Mv, B, w);
            sW[r * 68 + j] = __uint_as_float(f2tf32(w));
        }
        // V slab natural layout: sV[k][n], n = d (Vr) | 64+d (Vi)
        #pragma unroll
        for (int e2 = 0; e2 < 16; e2++) {
            int e = tid + e2 * 256;
            int k = e >> 6, d = e & 63;
            sV[k * 136 + d] = __uint_as_float(f2tf32(vr[(size_t)(m0 + k) * HD + d]));
            sV[k * 136 + 64 + d] = __uint_as_float(f2tf32(vi[(size_t)(m0 + k) * HD + d]));
        }
        __syncthreads();
        #pragma unroll
        for (int kc = 0; kc < 8; kc++) {
            int k0 = kc * 8;
            uint32_t a[2][4];
            #pragma unroll
            for (int mi = 0; mi < 2; mi++) {
                int rb = (wr * 32 + mi * 16 + g) * 68 + k0 + t;
                a[mi][0] = __float_as_uint(sW[rb]);
                a[mi][1] = __float_as_uint(sW[rb + 8 * 68]);
                a[mi][2] = __float_as_uint(sW[rb + 4]);
                a[mi][3] = __float_as_uint(sW[rb + 8 * 68 + 4]);
            }
            #pragma unroll
            for (int ni = 0; ni < 4; ni++) {
                int n = wc * 32 + ni * 8 + g;
                uint32_t b[2] = {__float_as_uint(sV[(k0 + t) * 136 + n]),
                                 __float_as_uint(sV[(k0 + t + 4) * 136 + n])};
                #pragma unroll
                for (int mi = 0; mi < 2; mi++) mma1688(acc[mi][ni], a[mi], b);
            }
        }
    }

    // Epilogue: dump O to SMEM (reuse sV), pair (Or,Oi), expert multiply
    __syncthreads();
    float* sO = sV;   // 64 rows x 136
    #pragma unroll
    for (int mi = 0; mi < 2; mi++)
        #pragma unroll
        for (int h = 0; h < 2; h++) {
            int r = wr * 32 + mi * 16 + g + h * 8;
            #pragma unroll
            for (int ni = 0; ni < 4; ni++) {
                int n = wc * 32 + ni * 8 + 2 * t;
                sO[r * 136 + n] = acc[mi][ni][h * 2];
                sO[r * 136 + n + 1] = acc[mi][ni][h * 2 + 1];
            }
        }
    __syncthreads();
    #pragma unroll
    for (int e2 = 0; e2 < 16; e2++) {
        int e = tid + e2 * 256;
        int r = e >> 6, d = e & 63;
        float a = sO[r * 136 + d];
        float b = sO[r * 136 + 64 + d];
        float scl = sscl[r], ssl = sssl[r];
        float cp = scp[d], sp = ssp[d];
        float epr = cp * scl - sp * ssl;
        float epi = sp * scl + cp * ssl;
        size_t ob = ((size_t)bh * SL + l0 + r) * HD + d;
        out[ob] = a * epr - b * epi;
        out[ob + PLANE] = a * epi + b * epr;
    }
}

// ---------------------------------------------------------------------------
extern "C" void kernel_launch(void* const* d_in, const int* in_sizes, int n_in,
                              void* d_out, int out_size) {
    const float* Qr = (const float*)d_in[0];
    const float* Qi = (const float*)d_in[1];
    const float* Kr = (const float*)d_in[2];
    const float* Ki = (const float*)d_in[3];
    const float* Vr = (const float*)d_in[4];
    const float* Vi = (const float*)d_in[5];
    float* out = (float*)d_out;

    cudaFuncSetAttribute(k_scores, cudaFuncAttributeMaxDynamicSharedMemorySize,
                         SC_SMEM_U32 * 4);
    cudaFuncSetAttribute(k_av, cudaFuncAttributeMaxDynamicSharedMemorySize,
                         AV_SMEM_FLOATS * 4);

    k_tables<<<5, 1024>>>();
    k_scores<<<dim3(16, 8, 32), 256, SC_SMEM_U32 * 4>>>(Qr, Qi, Kr, Ki);
    k_av<<<dim3(16, 32), 256, AV_SMEM_FLOATS * 4>>>(Vr, Vi, out);
}

// round 17
// speedup vs baseline: 1.2509x; 1.2509x over previous
#include <cuda_runtime.h>
#include <cuda_bf16.h>
#include <math.h>
#include <stdint.h>

#define SL 1024
#define HD 64
#define NBH 32
#define NS 4
#define LMAXC 2048
#define PLANE (NBH * SL * HD)

// Scratch (static device globals: allocation-free)
__device__ __nv_bfloat16 g_Mb[(size_t)NBH * SL * SL];    // |C|/8, bf16, 64MB
__device__ float g_a[NS * SL];                           // scale magnitude tables
__device__ float g_Zp[(size_t)NBH * 16 * 2 * NS * SL];   // Z partials (deterministic)
__device__ float g_sc[SL];                               // expert sum-cos per l
__device__ float g_ss[SL];                               // expert sum-sin per l

// ---------------------------------------------------------------------------
// tf32 mma.sync (sm_80+ baseline feature — compiles at plain sm_103 target)
// ---------------------------------------------------------------------------
__device__ __forceinline__ void mma1688(float* d, const uint32_t* a, const uint32_t* b) {
    asm volatile(
        "mma.sync.aligned.m16n8k8.row.col.f32.tf32.tf32.f32 "
        "{%0,%1,%2,%3}, {%4,%5,%6,%7}, {%8,%9}, {%0,%1,%2,%3};\n"
        : "+f"(d[0]), "+f"(d[1]), "+f"(d[2]), "+f"(d[3])
        : "r"(a[0]), "r"(a[1]), "r"(a[2]), "r"(a[3]), "r"(b[0]), "r"(b[1]));
}
__device__ __forceinline__ uint32_t f2tf32(float x) {
    uint32_t r;
    asm("cvt.rna.tf32.f32 %0, %1;" : "=r"(r) : "f"(x));
    return r;
}

// 1/sqrt Newton (FMA pipe, no MUFU): rel err ~1.7e-3 — below bf16 storage error.
__device__ __forceinline__ float rsqrt1(float x) {
    float r = __int_as_float(0x5f3759df - (__float_as_int(x) >> 1));
    return r * fmaf(-0.5f * x * r, r, 1.5f);
}

// ===========================================================================
// Kernel A: a_s[l] tables + expert sums. 5 blocks: 0-3 = scales, 4 = expert.
// ===========================================================================
__device__ __forceinline__ float pmag2f(float t) {
    return 3.f + 2.f * __cosf(t) + 2.f * __cosf(0.5f * t) + 2.f * __cosf(1.5f * t);
}

__global__ __launch_bounds__(1024) void k_tables() {
    __shared__ float red[1024];
    int l = threadIdx.x;
    int b = blockIdx.x;
    if (b < 4) {
        const float freqs[NS] = {1.f, 0.5f, 0.25f, 0.1f};
        float step = 6.283185307179586f * freqs[b] / (float)(LMAXC - 1);
        float p0 = pmag2f((float)l * step);
        float p1 = pmag2f((float)(l + 1024) * step);
        red[l] = p0 + p1;
        __syncthreads();
        for (int o = 512; o > 0; o >>= 1) {
            if (l < o) red[l] += red[l + o];
            __syncthreads();
        }
        g_a[b * SL + l] = sqrtf(fmaxf(p0, 0.f)) * rsqrtf(red[0]);
    } else {
        float t = (float)l * (6.283185307179586f / (float)(LMAXC - 1));
        float sc = 0.f, ss = 0.f;
        #pragma unroll
        for (int i = 0; i < 8; i++) {
            float fb = 0.1f * (float)i;
            float s0, c0, s1, c1, s2, c2;
            __sincosf((0.3f + fb) * t, &s0, &c0);
            __sincosf((0.2f + fb) * t, &s1, &c1);
            __sincosf((0.1f + fb) * t, &s2, &c2);
            sc += c0 + c1 + c2;
            ss += s0 + s1 + s2;
        }
        g_sc[l] = sc;
        g_ss[l] = ss;
    }
}

// ===========================================================================
// Kernel B (R6-exact, tf32): complex scores via tf32 mma.sync m16n8k8.
// CTA = 128 l x 64 m. Warps 4(row)x2(col), each 32x32. Epilogue: M=|c|/8 ->
// bf16 g_Mb, plus separable deg-2 softmax-Z partials.
// ===========================================================================
#define SC_SMEM_FLOATS 27136

__global__ __launch_bounds__(256) void k_scores(const float* __restrict__ Qr,
                                                const float* __restrict__ Qi,
                                                const float* __restrict__ Kr,
                                                const float* __restrict__ Ki) {
    extern __shared__ float sm[];
    float* sQr = sm;
    float* sQi = sm + 8704;
    float* sKr = sm + 17408;
    float* sKi = sm + 21760;
    float* sal = sm + 26112;
    float* sam = sm + 26624;
    float* sam2 = sm + 26880;

    int tid = threadIdx.x, wid = tid >> 5, lane = tid & 31;
    int g = lane >> 2, t = lane & 3;
    int mt = blockIdx.x, bh = blockIdx.z;
    int l0 = blockIdx.y * 128, m0 = mt * 64;
    int wr = wid & 3, wc = wid >> 2;

    // Stage Q (128x64) and K (64x64) tiles, stride 68 (conflict-free frags)
    for (int e = tid; e < 2048; e += 256) {
        int row = e >> 4, c4 = (e & 15) << 2;
        *(float4*)&sQr[row * 68 + c4] =
            *(const float4*)&Qr[((size_t)bh * SL + l0 + row) * HD + c4];
        *(float4*)&sQi[row * 68 + c4] =
            *(const float4*)&Qi[((size_t)bh * SL + l0 + row) * HD + c4];
    }
    for (int e = tid; e < 1024; e += 256) {
        int row = e >> 4, c4 = (e & 15) << 2;
        *(float4*)&sKr[row * 68 + c4] =
            *(const float4*)&Kr[((size_t)bh * SL + m0 + row) * HD + c4];
        *(float4*)&sKi[row * 68 + c4] =
            *(const float4*)&Ki[((size_t)bh * SL + m0 + row) * HD + c4];
    }
    for (int e = tid; e < 512; e += 256)
        sal[e] = g_a[(e >> 7) * SL + l0 + (e & 127)];
    if (tid < 256) {
        float v = g_a[(tid >> 6) * SL + m0 + (tid & 63)];
        sam[tid] = v;
        sam2[tid] = v * v;
    }
    __syncthreads();

    float cr[2][4][4] = {}, ci[2][4][4] = {};
    #pragma unroll
    for (int kc = 0; kc < 8; kc++) {
        int k0 = kc * 8;
        uint32_t aR[2][4], aI[2][4], aIn[2][4];
        #pragma unroll
        for (int mi = 0; mi < 2; mi++) {
            int rb = (wr * 32 + mi * 16 + g) * 68 + k0 + t;
            aR[mi][0] = __float_as_uint(sQr[rb]);
            aR[mi][1] = __float_as_uint(sQr[rb + 8 * 68]);
            aR[mi][2] = __float_as_uint(sQr[rb + 4]);
            aR[mi][3] = __float_as_uint(sQr[rb + 8 * 68 + 4]);
            aI[mi][0] = __float_as_uint(sQi[rb]);
            aI[mi][1] = __float_as_uint(sQi[rb + 8 * 68]);
            aI[mi][2] = __float_as_uint(sQi[rb + 4]);
            aI[mi][3] = __float_as_uint(sQi[rb + 8 * 68 + 4]);
            #pragma unroll
            for (int q = 0; q < 4; q++) aIn[mi][q] = aI[mi][q] ^ 0x80000000u;
        }
        #pragma unroll
        for (int ni = 0; ni < 4; ni++) {
            int nb = (wc * 32 + ni * 8 + g) * 68 + k0 + t;
            uint32_t bR[2] = {__float_as_uint(sKr[nb]), __float_as_uint(sKr[nb + 4])};
            uint32_t bI[2] = {__float_as_uint(sKi[nb]), __float_as_uint(sKi[nb + 4])};
            #pragma unroll
            for (int mi = 0; mi < 2; mi++) {
                mma1688(cr[mi][ni], aR[mi], bR);
                mma1688(cr[mi][ni], aIn[mi], bI);
                mma1688(ci[mi][ni], aR[mi], bI);
                mma1688(ci[mi][ni], aI[mi], bR);
            }
        }
    }

    // Epilogue: M -> bf16 g_Mb + separable deg-2 Z partials
    float S1[4][4] = {}, S2[4][4] = {};   // [ridx][s]
    size_t mrow0 = ((size_t)bh * SL + l0) * SL + m0 + wc * 32;
    #pragma unroll
    for (int ni = 0; ni < 4; ni++) {
        int c0 = ni * 8 + 2 * t;          // col within warp's 32
        float a0[4], a1[4], b0[4], b1[4];
        #pragma unroll
        for (int s = 0; s < 4; s++) {
            a0[s] = sam[s * 64 + wc * 32 + c0];
            a1[s] = sam[s * 64 + wc * 32 + c0 + 1];
            b0[s] = sam2[s * 64 + wc * 32 + c0];
            b1[s] = sam2[s * 64 + wc * 32 + c0 + 1];
        }
        #pragma unroll
        for (int mi = 0; mi < 2; mi++) {
            #pragma unroll
            for (int h = 0; h < 2; h++) {
                int ridx = mi * 2 + h;
                int row = wr * 32 + mi * 16 + g + h * 8;
                float x0 = cr[mi][ni][h * 2], y0 = ci[mi][ni][h * 2];
                float x1 = cr[mi][ni][h * 2 + 1], y1 = ci[mi][ni][h * 2 + 1];
                float h20 = fmaxf(fmaf(x0, x0, y0 * y0), 1e-30f);
                float h21 = fmaxf(fmaf(x1, x1, y1 * y1), 1e-30f);
                float Mv0 = h20 * rsqrt1(h20) * 0.125f;
                float Mv1 = h21 * rsqrt1(h21) * 0.125f;
                float M20 = h20 * 0.015625f;      // Mv^2
                float M21 = h21 * 0.015625f;
                *(__nv_bfloat162*)&g_Mb[mrow0 + (size_t)row * SL + c0] =
                    __floats2bfloat162_rn(Mv0, Mv1);
                #pragma unroll
                for (int s = 0; s < 4; s++) {
                    S1[ridx][s] = fmaf(a0[s], Mv0, fmaf(a1[s], Mv1, S1[ridx][s]));
                    S2[ridx][s] = fmaf(b0[s], M20, fmaf(b1[s], M21, S2[ridx][s]));
                }
            }
        }
    }
    #pragma unroll
    for (int ridx = 0; ridx < 4; ridx++)
        #pragma unroll
        for (int s = 0; s < 4; s++) {
            S1[ridx][s] += __shfl_xor_sync(0xffffffffu, S1[ridx][s], 1);
            S1[ridx][s] += __shfl_xor_sync(0xffffffffu, S1[ridx][s], 2);
            S2[ridx][s] += __shfl_xor_sync(0xffffffffu, S2[ridx][s], 1);
            S2[ridx][s] += __shfl_xor_sync(0xffffffffu, S2[ridx][s], 2);
        }
    if (t == 0) {
        #pragma unroll
        for (int ridx = 0; ridx < 4; ridx++) {
            int row = wr * 32 + (ridx >> 1) * 16 + g + (ridx & 1) * 8;
            #pragma unroll
            for (int s = 0; s < 4; s++) {
                float cl = sal[s * 128 + row];
                float z = fmaf(cl, S1[ridx][s], 32.f);
                z = fmaf(0.5f * cl * cl, S2[ridx][s], z);
                g_Zp[((((size_t)bh * 16 + mt) * 2 + wc) * 4 + s) * SL + l0 + row] = z;
            }
        }
    }
}

// ===========================================================================
// Kernel C (smem diet): O = W @ [Vr|Vi] via tf32 mma.sync; V natural [m][d]
// layout (conflict-free); W on the fly (separable deg-2, a_m^2 recomputed);
// 70.3 KB smem -> 3 CTAs/SM. SMEM epilogue pairs Or/Oi for expert multiply.
// CTA = 64 l x 128 n; warps 2(l)x4(n); 16 key-slabs of 64.
// ===========================================================================
#define AV_SMEM_FLOATS 17984

__global__ __launch_bounds__(256) void k_av(const float* __restrict__ Vr,
                                            const float* __restrict__ Vi,
                                            float* __restrict__ out) {
    extern __shared__ float sm[];
    float* sW = sm;
    float* sV = sm + 4352;
    float* samF = sm + 13056;
    float* T0 = sm + 17152;
    float* R1 = sm + 17216;
    float* R2 = sm + 17472;
    float* scp = sm + 17728;
    float* ssp = sm + 17792;
    float* sscl = sm + 17856;
    float* sssl = sm + 17920;

    int tid = threadIdx.x, wid = tid >> 5, lane = tid & 31;
    int g = lane >> 2, t = lane & 3;
    int bh = blockIdx.y, l0 = blockIdx.x * 64;
    int wr = wid & 1, wc = wid >> 1;
    const float KC = 0.00225527461f;   // 0.5 / sqrt(2048 * 24)

    for (int e = tid; e < 4096; e += 256)
        samF[e] = g_a[(e >> 10) * SL + (e & 1023)];
    {   // per-(s,row) Z reduction, parallel over 256 threads
        int s = tid >> 6, r = tid & 63, l = l0 + r;
        float zt = 0.f;
        #pragma unroll 8
        for (int p = 0; p < 32; p++)
            zt += g_Zp[(((size_t)bh * 32 + p) * 4 + s) * SL + l];
        float riz = 1.0f / zt;
        float cl = g_a[s * SL + l];
        sW[s * 64 + r] = riz;                       // temp for T0 reduce
        R1[s * 64 + r] = riz * cl;
        R2[s * 64 + r] = 0.5f * riz * cl * cl;
    }
    if (tid < 64) {
        int r = tid, l = l0 + r;
        float sp, cp;
        __sincosf(0.09817477042f * (float)r, &sp, &cp);   // 2*pi/64 * d
        scp[r] = cp;
        ssp[r] = sp;
        sscl[r] = g_sc[l] * KC;
        sssl[r] = g_ss[l] * KC;
    }
    __syncthreads();
    if (tid < 64)
        T0[tid] = sW[tid] + sW[64 + tid] + sW[128 + tid] + sW[192 + tid];

    float acc[2][4][4] = {};
    const __nv_bfloat16* Mrow = g_Mb + ((size_t)bh * SL + l0) * SL;
    const float* vr = Vr + (size_t)bh * SL * HD;
    const float* vi = Vi + (size_t)bh * SL * HD;
    int j = tid & 63, rbase = tid >> 6;

    for (int it = 0; it < 16; it++) {
        int m0 = it * 64;
        __syncthreads();   // protect prev-iter sW/sV reads (and T0 init)
        // W tile 64l x 64m: w = T0[r] + M*A + M^2*B   (a_m^2 recomputed)
        float amv[4], am2v[4];
        #pragma unroll
        for (int s = 0; s < 4; s++) {
            amv[s] = samF[s * 1024 + m0 + j];
            am2v[s] = amv[s] * amv[s];
        }
        #pragma unroll
        for (int i = 0; i < 16; i++) {
            int r = rbase + i * 4;   // warp-uniform row
            float Mv = __bfloat162float(Mrow[(size_t)r * SL + m0 + j]);
            float A = 0.f, B = 0.f;
            #pragma unroll
            for (int s = 0; s < 4; s++) {
                A = fmaf(R1[s * 64 + r], amv[s], A);
                B = fmaf(R2[s * 64 + r], am2v[s], B);
            }
            float w = fmaf(Mv, A, T0[r]);
            w = fmaf(Mv * Mv, B, w);
            sW[r * 68 + j] = __uint_as_float(f2tf32(w));
        }
        // V slab natural layout: sV[k][n], n = d (Vr) | 64+d (Vi)
        #pragma unroll
        for (int e2 = 0; e2 < 16; e2++) {
            int e = tid + e2 * 256;
            int k = e >> 6, d = e & 63;
            sV[k * 136 + d] = __uint_as_float(f2tf32(vr[(size_t)(m0 + k) * HD + d]));
            sV[k * 136 + 64 + d] = __uint_as_float(f2tf32(vi[(size_t)(m0 + k) * HD + d]));
        }
        __syncthreads();
        #pragma unroll
        for (int kc = 0; kc < 8; kc++) {
            int k0 = kc * 8;
            uint32_t a[2][4];
            #pragma unroll
            for (int mi = 0; mi < 2; mi++) {
                int rb = (wr * 32 + mi * 16 + g) * 68 + k0 + t;
                a[mi][0] = __float_as_uint(sW[rb]);
                a[mi][1] = __float_as_uint(sW[rb + 8 * 68]);
                a[mi][2] = __float_as_uint(sW[rb + 4]);
                a[mi][3] = __float_as_uint(sW[rb + 8 * 68 + 4]);
            }
            #pragma unroll
            for (int ni = 0; ni < 4; ni++) {
                int n = wc * 32 + ni * 8 + g;
                uint32_t b[2] = {__float_as_uint(sV[(k0 + t) * 136 + n]),
                                 __float_as_uint(sV[(k0 + t + 4) * 136 + n])};
                #pragma unroll
                for (int mi = 0; mi < 2; mi++) mma1688(acc[mi][ni], a[mi], b);
            }
        }
    }

    // Epilogue: dump O to SMEM (reuse sV), pair (Or,Oi), expert multiply
    __syncthreads();
    float* sO = sV;   // 64 rows x 136
    #pragma unroll
    for (int mi = 0; mi < 2; mi++)
        #pragma unroll
        for (int h = 0; h < 2; h++) {
            int r = wr * 32 + mi * 16 + g + h * 8;
            #pragma unroll
            for (int ni = 0; ni < 4; ni++) {
                int n = wc * 32 + ni * 8 + 2 * t;
                sO[r * 136 + n] = acc[mi][ni][h * 2];
                sO[r * 136 + n + 1] = acc[mi][ni][h * 2 + 1];
            }
        }
    __syncthreads();
    #pragma unroll
    for (int e2 = 0; e2 < 16; e2++) {
        int e = tid + e2 * 256;
        int r = e >> 6, d = e & 63;
        float a = sO[r * 136 + d];
        float b = sO[r * 136 + 64 + d];
        float scl = sscl[r], ssl = sssl[r];
        float cp = scp[d], sp = ssp[d];
        float epr = cp * scl - sp * ssl;
        float epi = sp * scl + cp * ssl;
        size_t ob = ((size_t)bh * SL + l0 + r) * HD + d;
        out[ob] = a * epr - b * epi;
        out[ob + PLANE] = a * epi + b * epr;
    }
}

// ---------------------------------------------------------------------------
extern "C" void kernel_launch(void* const* d_in, const int* in_sizes, int n_in,
                              void* d_out, int out_size) {
    const float* Qr = (const float*)d_in[0];
    const float* Qi = (const float*)d_in[1];
    const float* Kr = (const float*)d_in[2];
    const float* Ki = (const float*)d_in[3];
    const float* Vr = (const float*)d_in[4];
    const float* Vi = (const float*)d_in[5];
    float* out = (float*)d_out;

    cudaFuncSetAttribute(k_scores, cudaFuncAttributeMaxDynamicSharedMemorySize,
                         SC_SMEM_FLOATS * 4);
    cudaFuncSetAttribute(k_av, cudaFuncAttributeMaxDynamicSharedMemorySize,
                         AV_SMEM_FLOATS * 4);

    k_tables<<<5, 1024>>>();
    k_scores<<<dim3(16, 8, 32), 256, SC_SMEM_FLOATS * 4>>>(Qr, Qi, Kr, Ki);
    k_av<<<dim3(16, 32), 256, AV_SMEM_FLOATS * 4>>>(Vr, Vi, out);
}